// round 6
// baseline (speedup 1.0000x reference)
#include <cuda_runtime.h>
#include <math_constants.h>
#include <cstdint>

#define B_  4
#define L_  4096
#define D_  256
#define BL_ (B_ * L_)

// Scratch (allocation-free device globals), tf32-rounded values.
__device__ __align__(1024) float g_Q[BL_ * D_];        // [row][d]
__device__ __align__(1024) float g_Kt[B_ * D_ * L_];   // [b][d][key]

// ---------------------------------------------------------------------------
// helpers
// ---------------------------------------------------------------------------
__device__ __forceinline__ unsigned long long fma2(unsigned long long a,
                                                   unsigned long long b,
                                                   unsigned long long c) {
    unsigned long long d;
    asm("fma.rn.f32x2 %0, %1, %2, %3;" : "=l"(d) : "l"(a), "l"(b), "l"(c));
    return d;
}

__device__ __forceinline__ uint32_t smem_u32(const void* p) {
    uint32_t a;
    asm("{ .reg .u64 t; cvta.to.shared.u64 t, %1; cvt.u32.u64 %0, t; }"
        : "=r"(a) : "l"(p));
    return a;
}

__device__ __forceinline__ float tf32r(float x) {
    uint32_t u;
    asm("cvt.rna.tf32.f32 %0, %1;" : "=r"(u) : "f"(x));
    return __uint_as_float(u);
}

__device__ __forceinline__ float ex2f(float x) {
    float y;
    asm("ex2.approx.f32 %0, %1;" : "=f"(y) : "f"(x));
    return y;
}

__device__ __forceinline__ void cp16(uint32_t dst, const void* src) {
    asm volatile("cp.async.cg.shared.global [%0], [%1], 16;"
                 :: "r"(dst), "l"(src) : "memory");
}
__device__ __forceinline__ void cp_commit() {
    asm volatile("cp.async.commit_group;" ::: "memory");
}
__device__ __forceinline__ void cp_wait2() {
    asm volatile("cp.async.wait_group 2;" ::: "memory");
}

__device__ __forceinline__ uint32_t lds32(uint32_t a) {
    uint32_t v;
    asm volatile("ld.shared.b32 %0, [%1];" : "=r"(v) : "r"(a));
    return v;
}

#define MMA_TF32(d, a, b0, b1) \
    asm volatile("mma.sync.aligned.m16n8k8.row.col.f32.tf32.tf32.f32 " \
                 "{%0,%1,%2,%3},{%4,%5,%6,%7},{%8,%9},{%0,%1,%2,%3};" \
                 : "+f"((d)[0]), "+f"((d)[1]), "+f"((d)[2]), "+f"((d)[3]) \
                 : "r"((a)[0]), "r"((a)[1]), "r"((a)[2]), "r"((a)[3]), \
                   "r"(b0), "r"(b1))

// ---------------------------------------------------------------------------
// Kernel 1: y[r][c] = sum_d X[r][d] * W[c][d], row-L2-normalize, tf32-round.
// grid.y==0: write g_Q row-major. grid.y==1: write g_Kt transposed [d][key].
// ---------------------------------------------------------------------------
__global__ void __launch_bounds__(128)
proj_norm_kernel(const float* __restrict__ X, const float* __restrict__ Wqp,
                 const float* __restrict__ Wkp) {
    __shared__ __align__(16) float X_s[32][34];
    __shared__ __align__(16) float W_s[256][34];

    const float* __restrict__ W = blockIdx.y ? Wkp : Wqp;

    const int tid = threadIdx.x;
    const int rg  = tid >> 5;
    const int cg  = tid & 31;
    const int row0 = blockIdx.x * 32;

    unsigned long long acc2[8][8];
#pragma unroll
    for (int i = 0; i < 8; i++)
#pragma unroll
        for (int j = 0; j < 8; j++) acc2[i][j] = 0ull;

    for (int d0 = 0; d0 < D_; d0 += 32) {
#pragma unroll
        for (int t = 0; t < 2; t++) {
            int idx = tid + t * 128;
            int r = idx >> 3;
            int d4 = (idx & 7) * 4;
            float4 v = *(const float4*)&X[(row0 + r) * D_ + d0 + d4];
            X_s[r][d4 + 0] = v.x; X_s[r][d4 + 1] = v.y;
            X_s[r][d4 + 2] = v.z; X_s[r][d4 + 3] = v.w;
        }
#pragma unroll
        for (int t = 0; t < 16; t++) {
            int idx = tid + t * 128;
            int c = idx >> 3;
            int d4 = (idx & 7) * 4;
            float4 v = *(const float4*)&W[c * D_ + d0 + d4];
            W_s[c][d4 + 0] = v.x; W_s[c][d4 + 1] = v.y;
            W_s[c][d4 + 2] = v.z; W_s[c][d4 + 3] = v.w;
        }
        __syncthreads();
#pragma unroll 4
        for (int d = 0; d < 32; d += 2) {
            unsigned long long w2[8], x2[8];
#pragma unroll
            for (int cc = 0; cc < 8; cc++)
                w2[cc] = *(const unsigned long long*)&W_s[cc * 32 + cg][d];
#pragma unroll
            for (int ii = 0; ii < 8; ii++)
                x2[ii] = *(const unsigned long long*)&X_s[ii * 4 + rg][d];
#pragma unroll
            for (int ii = 0; ii < 8; ii++)
#pragma unroll
                for (int cc = 0; cc < 8; cc++)
                    acc2[ii][cc] = fma2(x2[ii], w2[cc], acc2[ii][cc]);
        }
        __syncthreads();
    }

    // T overlay for the K-transpose path (W_s is dead now). Stride 33.
    float* T = &W_s[0][0];

#pragma unroll
    for (int ii = 0; ii < 8; ii++) {
        float dot[8];
        float sq = 0.f;
#pragma unroll
        for (int cc = 0; cc < 8; cc++) {
            unsigned long long v = acc2[ii][cc];
            dot[cc] = __uint_as_float((unsigned)v) +
                      __uint_as_float((unsigned)(v >> 32));
            sq = fmaf(dot[cc], dot[cc], sq);
        }
#pragma unroll
        for (int off = 16; off > 0; off >>= 1)
            sq += __shfl_xor_sync(0xffffffffu, sq, off);
        float scale = 1.0f / fmaxf(sqrtf(sq), 1e-12f);
        int rowl = ii * 4 + rg;
        if (blockIdx.y == 0) {
            int row = row0 + rowl;
#pragma unroll
            for (int cc = 0; cc < 8; cc++)
                g_Q[row * D_ + cc * 32 + cg] = tf32r(dot[cc] * scale);
        } else {
#pragma unroll
            for (int cc = 0; cc < 8; cc++)
                T[(cc * 32 + cg) * 33 + rowl] = tf32r(dot[cc] * scale);
        }
    }

    if (blockIdx.y == 1) {
        __syncthreads();
        int bb = row0 >> 12;          // batch
        int l0 = row0 & 4095;         // key offset within batch
        float* base = g_Kt + ((size_t)bb * D_) * L_ + l0;
#pragma unroll
        for (int it = 0; it < 64; it++) {
            int idx = tid + it * 128;       // 0..8191
            int d = idx >> 5, key = idx & 31;
            base[(size_t)d * L_ + key] = T[d * 33 + key];
        }
    }
}

// ---------------------------------------------------------------------------
// Kernel 2: flash attention via mma.sync tf32.
// CTA: 128 q x all keys; 512 threads = 16 warps (warpm 0..3, warpn 0..3).
// Warp tile 32(m) x 32(n); K streamed in 32-d x 128-key chunks (cp.async ring 4).
// Scores ~N(0, 0.625) (unit q,k, temp 10) -> clip is a no-op, no running max.
// ---------------------------------------------------------------------------
#define QSTRIDE 260
#define KSTRIDE 136
#define SLOT_B  (32 * KSTRIDE * 4)          /* 17408 */
#define SM_Q    0
#define SM_K    133120                      /* 128*260*4 */
#define SM_C    (SM_K + 4 * SLOT_B)         /* 202752 */
#define SM_R    (SM_C + 1024)               /* 203776 */
#define SM_TOT  (SM_R + 8192)               /* 211968 */

#define SCALE_EX2 14.4269504088896340f      /* 10 * log2(e) */

__global__ void __launch_bounds__(512, 1)
attn_kernel(const float* __restrict__ coords,
            const float* __restrict__ alpha_p,
            float* __restrict__ out_new,
            float* __restrict__ out_disp) {
    extern __shared__ __align__(1024) char smem[];
    const uint32_t sb = smem_u32(smem);
    const int tid  = threadIdx.x;
    const int lane = tid & 31;
    const int warp = tid >> 5;
    const int warpm = warp & 3, warpn = warp >> 2;   // 4 x 4 warp grid
    const int g  = lane >> 2, t4 = lane & 3;
    const int b  = blockIdx.y;
    const int q0 = blockIdx.x * 128;

    const float* __restrict__ Qg  = g_Q + (size_t)(b * L_ + q0) * D_;
    const float* __restrict__ Ktg = g_Kt + (size_t)b * D_ * L_;
    const float2* __restrict__ Cg2 = (const float2*)coords + (size_t)b * L_;

    // ---- prologue: Q tile + first 3 K chunks via cp.async ----
#pragma unroll
    for (int i = 0; i < 16; i++) {
        int seg = tid + 512 * i;            // 0..8191
        int row = seg >> 6, o = seg & 63;   // 64 x 16B per row
        cp16(sb + SM_Q + row * (QSTRIDE * 4) + o * 16, Qg + row * D_ + o * 4);
    }
    cp_commit();
#pragma unroll
    for (int gc = 0; gc < 3; gc++) {
        int t0 = (gc >> 3) * 128, d0 = (gc & 7) * 32;
        uint32_t slot = sb + SM_K + (gc & 3) * SLOT_B;
        const float* src = Ktg + (size_t)d0 * L_ + t0;
#pragma unroll
        for (int i = 0; i < 2; i++) {
            int seg = tid + 512 * i;
            int dr = seg >> 5, ko = (seg & 31) * 4;
            cp16(slot + dr * (KSTRIDE * 4) + ko * 4, src + (size_t)dr * L_ + ko);
        }
        cp_commit();
    }

    float l[4], ax[4], ay[4];
#pragma unroll
    for (int s = 0; s < 4; s++) { l[s] = 0.f; ax[s] = 0.f; ay[s] = 0.f; }

    for (int t = 0; t < 32; t++) {
        __syncthreads();                    // prev tile epilogue done w/ C_s
        if (tid < 128)
            ((float2*)(smem + SM_C))[tid] = Cg2[t * 128 + tid];

        float S[2][4][4];
#pragma unroll
        for (int mt = 0; mt < 2; mt++)
#pragma unroll
            for (int nb = 0; nb < 4; nb++)
#pragma unroll
                for (int r = 0; r < 4; r++) S[mt][nb][r] = 0.f;

        for (int c8 = 0; c8 < 8; c8++) {
            const int gc = t * 8 + c8;
            cp_wait2();
            __syncthreads();
            // prefetch chunk gc+3 into slot (gc+3)&3 (== (gc-1)&3, now free)
            if (gc + 3 < 256) {
                int nc = gc + 3;
                int t0 = (nc >> 3) * 128, d0 = (nc & 7) * 32;
                uint32_t slot = sb + SM_K + (nc & 3) * SLOT_B;
                const float* src = Ktg + (size_t)d0 * L_ + t0;
#pragma unroll
                for (int i = 0; i < 2; i++) {
                    int seg = tid + 512 * i;
                    int dr = seg >> 5, ko = (seg & 31) * 4;
                    cp16(slot + dr * (KSTRIDE * 4) + ko * 4,
                         src + (size_t)dr * L_ + ko);
                }
            }
            cp_commit();

            const uint32_t slot = sb + SM_K + (gc & 3) * SLOT_B;
#pragma unroll
            for (int ds = 0; ds < 4; ds++) {
                uint32_t a[2][4];
                const int colb = (c8 * 32 + ds * 8 + t4) * 4;
#pragma unroll
                for (int mt = 0; mt < 2; mt++) {
                    uint32_t qb = sb + SM_Q +
                        (warpm * 32 + mt * 16 + g) * (QSTRIDE * 4) + colb;
                    a[mt][0] = lds32(qb);
                    a[mt][1] = lds32(qb + 8 * QSTRIDE * 4);
                    a[mt][2] = lds32(qb + 16);
                    a[mt][3] = lds32(qb + 8 * QSTRIDE * 4 + 16);
                }
                uint32_t kb = slot + (ds * 8 + t4) * (KSTRIDE * 4) +
                              (warpn * 32 + g) * 4;
#pragma unroll
                for (int nb = 0; nb < 4; nb++) {
                    uint32_t b0 = lds32(kb + nb * 32);
                    uint32_t b1 = lds32(kb + nb * 32 + 4 * KSTRIDE * 4);
                    MMA_TF32(S[0][nb], a[0], b0, b1);
                    MMA_TF32(S[1][nb], a[1], b0, b1);
                }
            }
        }

        // ---- epilogue: p = 2^(s*10*log2e); accumulate l, ax, ay ----
        // c0/c1 of mma tile (m-row g) sit at key cols warpn*32 + nb*8 + 2*t4 (+1);
        // as float4 over float2-coords: index warpn*16 + nb*4 + t4.
        const float4* __restrict__ C4 = (const float4*)(smem + SM_C);
#pragma unroll
        for (int mt = 0; mt < 2; mt++) {
            const int s0 = mt * 2, s1 = mt * 2 + 1;
#pragma unroll
            for (int nb = 0; nb < 4; nb++) {
                float4 cc = C4[warpn * 16 + nb * 4 + t4];
                float p0 = ex2f(S[mt][nb][0] * SCALE_EX2);
                float p1 = ex2f(S[mt][nb][1] * SCALE_EX2);
                float p2 = ex2f(S[mt][nb][2] * SCALE_EX2);
                float p3 = ex2f(S[mt][nb][3] * SCALE_EX2);
                l[s0] += p0 + p1;
                ax[s0] = fmaf(p0, cc.x, ax[s0]); ay[s0] = fmaf(p0, cc.y, ay[s0]);
                ax[s0] = fmaf(p1, cc.z, ax[s0]); ay[s0] = fmaf(p1, cc.w, ay[s0]);
                l[s1] += p2 + p3;
                ax[s1] = fmaf(p2, cc.x, ax[s1]); ay[s1] = fmaf(p2, cc.y, ay[s1]);
                ax[s1] = fmaf(p3, cc.z, ax[s1]); ay[s1] = fmaf(p3, cc.w, ay[s1]);
            }
        }
    }

    // ---- cross-lane + cross-warpn reduction, then output ----
    float4* __restrict__ red = (float4*)(smem + SM_R);
#pragma unroll
    for (int s = 0; s < 4; s++) {
#pragma unroll
        for (int off = 1; off < 4; off <<= 1) {
            l[s]  += __shfl_xor_sync(0xffffffffu, l[s],  off);
            ax[s] += __shfl_xor_sync(0xffffffffu, ax[s], off);
            ay[s] += __shfl_xor_sync(0xffffffffu, ay[s], off);
        }
        if (t4 == 0) {
            int rowl = warpm * 32 + (s >> 1) * 16 + (s & 1) * 8 + g;
            red[warpn * 128 + rowl] = make_float4(l[s], ax[s], ay[s], 0.f);
        }
    }
    __syncthreads();

    if (tid < 128) {
        float4 r0 = red[tid], r1 = red[128 + tid];
        float4 r2 = red[256 + tid], r3 = red[384 + tid];
        float lv  = (r0.x + r1.x) + (r2.x + r3.x);
        float axv = (r0.y + r1.y) + (r2.y + r3.y);
        float ayv = (r0.z + r1.z) + (r2.z + r3.z);
        float a = 1.0f / (1.0f + __expf(-alpha_p[0]));
        float inv = 1.0f / lv;
        float wx = axv * inv, wy = ayv * inv;
        float2 c = Cg2[q0 + tid];
        float nx = a * wx + (1.0f - a) * c.x;
        float ny = a * wy + (1.0f - a) * c.y;
        size_t o = ((size_t)b * L_ + q0 + tid) * 2;
        out_new[o + 0]  = nx;
        out_new[o + 1]  = ny;
        out_disp[o + 0] = nx - c.x;
        out_disp[o + 1] = ny - c.y;
    }
}

// ---------------------------------------------------------------------------
// Inputs: latents, current_coords, Wq, Wk, alpha_raw, layer_idx.
// Output: concat(new_coords[B,L,2], displacement[B,L,2]) fp32.
// ---------------------------------------------------------------------------
extern "C" void kernel_launch(void* const* d_in, const int* in_sizes, int n_in,
                              void* d_out, int out_size) {
    const float* latents   = (const float*)d_in[0];
    const float* coords    = (const float*)d_in[1];
    const float* Wq        = (const float*)d_in[2];
    const float* Wk        = (const float*)d_in[3];
    const float* alpha_raw = (const float*)d_in[4];
    float* out = (float*)d_out;

    proj_norm_kernel<<<dim3(BL_ / 32, 2), 128>>>(latents, Wq, Wk);

    cudaFuncSetAttribute(attn_kernel,
                         cudaFuncAttributeMaxDynamicSharedMemorySize, SM_TOT);
    attn_kernel<<<dim3(L_ / 128, B_), 512, SM_TOT>>>(
        coords, alpha_raw, out, out + BL_ * 2);
}

// round 7
// speedup vs baseline: 1.2910x; 1.2910x over previous
#include <cuda_runtime.h>
#include <cuda_bf16.h>
#include <math_constants.h>
#include <cstdint>

#define B_  4
#define L_  4096
#define D_  256
#define BL_ (B_ * L_)

// Scratch (allocation-free device globals), bf16, pair-interleaved d-layout:
// within each 16-d group, pair order [0,4,1,5,2,6,3,7] (pair j at slot
// 2j if j<4 else 2(j-4)+1), so mma fragment words are 8B-contiguous.
__device__ __align__(1024) __nv_bfloat16 g_Q[BL_ * D_];
__device__ __align__(1024) __nv_bfloat16 g_KB[BL_ * D_];

// ---------------------------------------------------------------------------
// helpers
// ---------------------------------------------------------------------------
__device__ __forceinline__ unsigned long long fma2(unsigned long long a,
                                                   unsigned long long b,
                                                   unsigned long long c) {
    unsigned long long d;
    asm("fma.rn.f32x2 %0, %1, %2, %3;" : "=l"(d) : "l"(a), "l"(b), "l"(c));
    return d;
}

__device__ __forceinline__ uint32_t smem_u32(const void* p) {
    uint32_t a;
    asm("{ .reg .u64 t; cvta.to.shared.u64 t, %1; cvt.u32.u64 %0, t; }"
        : "=r"(a) : "l"(p));
    return a;
}

__device__ __forceinline__ float ex2f(float x) {
    float y;
    asm("ex2.approx.f32 %0, %1;" : "=f"(y) : "f"(x));
    return y;
}

__device__ __forceinline__ void cp16(uint32_t dst, const void* src) {
    asm volatile("cp.async.cg.shared.global [%0], [%1], 16;"
                 :: "r"(dst), "l"(src) : "memory");
}
__device__ __forceinline__ void cp_commit() {
    asm volatile("cp.async.commit_group;" ::: "memory");
}
__device__ __forceinline__ void cp_wait2() {
    asm volatile("cp.async.wait_group 2;" ::: "memory");
}

__device__ __forceinline__ void lds64(uint32_t& v0, uint32_t& v1, uint32_t a) {
    asm volatile("ld.shared.v2.b32 {%0, %1}, [%2];"
                 : "=r"(v0), "=r"(v1) : "r"(a));
}

#define MMA_BF16(d, a0, a1, a2, a3, b0, b1) \
    asm volatile("mma.sync.aligned.m16n8k16.row.col.f32.bf16.bf16.f32 " \
                 "{%0,%1,%2,%3},{%4,%5,%6,%7},{%8,%9},{%0,%1,%2,%3};" \
                 : "+f"((d)[0]), "+f"((d)[1]), "+f"((d)[2]), "+f"((d)[3]) \
                 : "r"(a0), "r"(a1), "r"(a2), "r"(a3), "r"(b0), "r"(b1))

// ---------------------------------------------------------------------------
// Kernel 1: y[r][c] = sum_d X[r][d] * W[c][d], row-L2-normalize, bf16-pack
// with pair-interleaved d-layout. grid.y: 0 -> g_Q, 1 -> g_KB.
// ---------------------------------------------------------------------------
__global__ void __launch_bounds__(128)
proj_norm_kernel(const float* __restrict__ X, const float* __restrict__ Wqp,
                 const float* __restrict__ Wkp) {
    __shared__ __align__(16) float X_s[32][34];
    __shared__ __align__(16) float W_s[256][34];

    const float* __restrict__ W = blockIdx.y ? Wkp : Wqp;

    const int tid = threadIdx.x;
    const int rg  = tid >> 5;
    const int cg  = tid & 31;
    const int row0 = blockIdx.x * 32;

    unsigned long long acc2[8][8];
#pragma unroll
    for (int i = 0; i < 8; i++)
#pragma unroll
        for (int j = 0; j < 8; j++) acc2[i][j] = 0ull;

    for (int d0 = 0; d0 < D_; d0 += 32) {
#pragma unroll
        for (int t = 0; t < 2; t++) {
            int idx = tid + t * 128;
            int r = idx >> 3;
            int d4 = (idx & 7) * 4;
            float4 v = *(const float4*)&X[(row0 + r) * D_ + d0 + d4];
            X_s[r][d4 + 0] = v.x; X_s[r][d4 + 1] = v.y;
            X_s[r][d4 + 2] = v.z; X_s[r][d4 + 3] = v.w;
        }
#pragma unroll
        for (int t = 0; t < 16; t++) {
            int idx = tid + t * 128;
            int c = idx >> 3;
            int d4 = (idx & 7) * 4;
            float4 v = *(const float4*)&W[c * D_ + d0 + d4];
            W_s[c][d4 + 0] = v.x; W_s[c][d4 + 1] = v.y;
            W_s[c][d4 + 2] = v.z; W_s[c][d4 + 3] = v.w;
        }
        __syncthreads();
#pragma unroll 4
        for (int d = 0; d < 32; d += 2) {
            unsigned long long w2[8], x2[8];
#pragma unroll
            for (int cc = 0; cc < 8; cc++)
                w2[cc] = *(const unsigned long long*)&W_s[cc * 32 + cg][d];
#pragma unroll
            for (int ii = 0; ii < 8; ii++)
                x2[ii] = *(const unsigned long long*)&X_s[ii * 4 + rg][d];
#pragma unroll
            for (int ii = 0; ii < 8; ii++)
#pragma unroll
                for (int cc = 0; cc < 8; cc++)
                    acc2[ii][cc] = fma2(x2[ii], w2[cc], acc2[ii][cc]);
        }
        __syncthreads();
    }

    // Stage normalized fp32 into T[d][row] (stride 33 overlay on W_s).
    float* T = &W_s[0][0];

#pragma unroll
    for (int ii = 0; ii < 8; ii++) {
        float dot[8];
        float sq = 0.f;
#pragma unroll
        for (int cc = 0; cc < 8; cc++) {
            unsigned long long v = acc2[ii][cc];
            dot[cc] = __uint_as_float((unsigned)v) +
                      __uint_as_float((unsigned)(v >> 32));
            sq = fmaf(dot[cc], dot[cc], sq);
        }
#pragma unroll
        for (int off = 16; off > 0; off >>= 1)
            sq += __shfl_xor_sync(0xffffffffu, sq, off);
        float scale = 1.0f / fmaxf(sqrtf(sq), 1e-12f);
        int rowl = ii * 4 + rg;
#pragma unroll
        for (int cc = 0; cc < 8; cc++)
            T[(cc * 32 + cg) * 33 + rowl] = dot[cc] * scale;
    }
    __syncthreads();

    // Pack bf16x2 with pair-interleaving: phys pair-slot s in 16-d group g16
    // holds logical pair j = (s&1) ? (s>>1)+4 : (s>>1), d = g16*16 + 2*j.
    __nv_bfloat162* __restrict__ Out =
        (__nv_bfloat162*)(blockIdx.y ? g_KB : g_Q);
#pragma unroll
    for (int it = 0; it < 32; it++) {
        int idx = tid + it * 128;          // 0..4095
        int row = idx >> 7;                // 0..31
        int ps  = idx & 127;               // phys pair-slot in row
        int g16 = ps >> 3, s = ps & 7;
        int j = (s & 1) ? (s >> 1) + 4 : (s >> 1);
        int d = g16 * 16 + 2 * j;
        float lo = T[d * 33 + row];
        float hi = T[(d + 1) * 33 + row];
        Out[(size_t)(row0 + row) * 128 + ps] = __floats2bfloat162_rn(lo, hi);
    }
}

// ---------------------------------------------------------------------------
// Kernel 2: flash attention via mma.sync bf16 m16n8k16.
// CTA: 128 q x all keys; 256 threads = 8 warps (warpm 0..3, warpn 0..1).
// Warp tile 32(m) x 64(n); K streamed in 32-d x 128-key chunks (cp.async ring 4).
// Scores ~N(0, 0.625) (unit q,k, temp 10) -> clip is a no-op, no running max.
// ---------------------------------------------------------------------------
#define QST   528                            /* bytes per Q row (512 + 16) */
#define KST   80                             /* bytes per K row (64 + 16) */
#define SLOT_B (128 * KST)                   /* 10240 */
#define SM_Q   0
#define SM_K   (128 * QST)                   /* 67584 */
#define SM_C   (SM_K + 4 * SLOT_B)           /* 108544 */
#define SM_R   (SM_C + 1024)                 /* 109568 */
#define SM_TOT (SM_R + 4096)                 /* 113664 */

#define SCALE_EX2 14.4269504088896340f       /* 10 * log2(e) */

__global__ void __launch_bounds__(256, 1)
attn_kernel(const float* __restrict__ coords,
            const float* __restrict__ alpha_p,
            float* __restrict__ out_new,
            float* __restrict__ out_disp) {
    extern __shared__ __align__(1024) char smem[];
    const uint32_t sb = smem_u32(smem);
    const int tid  = threadIdx.x;
    const int lane = tid & 31;
    const int warp = tid >> 5;
    const int warpm = warp & 3, warpn = warp >> 2;   // 4 x 2 warp grid
    const int g  = lane >> 2, t4 = lane & 3;
    const int b  = blockIdx.y;
    const int q0 = blockIdx.x * 128;

    const __nv_bfloat16* __restrict__ Qg = g_Q + (size_t)(b * L_ + q0) * D_;
    const __nv_bfloat16* __restrict__ Kg = g_KB + (size_t)b * L_ * D_;
    const float2* __restrict__ Cg2 = (const float2*)coords + (size_t)b * L_;

    // ---- prologue: Q tile + first 3 K chunks via cp.async ----
#pragma unroll
    for (int i = 0; i < 16; i++) {
        int seg = tid + 256 * i;            // 0..4095 (32 x 16B per row)
        int row = seg >> 5, o = seg & 31;
        cp16(sb + SM_Q + row * QST + o * 16, Qg + row * D_ + o * 8);
    }
    cp_commit();
#pragma unroll
    for (int gc = 0; gc < 3; gc++) {
        int t0 = (gc >> 3) * 128, d0 = (gc & 7) * 32;
        uint32_t slot = sb + SM_K + (gc & 3) * SLOT_B;
#pragma unroll
        for (int i = 0; i < 2; i++) {
            int seg = tid + 256 * i;        // 0..511 (4 x 16B per key row)
            int kr = seg >> 2, o = seg & 3;
            cp16(slot + kr * KST + o * 16,
                 Kg + (size_t)(t0 + kr) * D_ + d0 + o * 8);
        }
        cp_commit();
    }

    float l[4], ax[4], ay[4];
#pragma unroll
    for (int s = 0; s < 4; s++) { l[s] = 0.f; ax[s] = 0.f; ay[s] = 0.f; }

    for (int t = 0; t < 32; t++) {
        __syncthreads();                    // prev tile epilogue done w/ C_s
        if (tid < 128)
            ((float2*)(smem + SM_C))[tid] = Cg2[t * 128 + tid];

        float S[2][8][4];
#pragma unroll
        for (int mt = 0; mt < 2; mt++)
#pragma unroll
            for (int nb = 0; nb < 8; nb++)
#pragma unroll
                for (int r = 0; r < 4; r++) S[mt][nb][r] = 0.f;

        for (int c8 = 0; c8 < 8; c8++) {
            const int gc = t * 8 + c8;
            cp_wait2();
            __syncthreads();
            // prefetch chunk gc+3 into slot (gc+3)&3 (== (gc-1)&3, now free)
            if (gc + 3 < 256) {
                int nc = gc + 3;
                int t0 = (nc >> 3) * 128, d0 = (nc & 7) * 32;
                uint32_t slot = sb + SM_K + (nc & 3) * SLOT_B;
#pragma unroll
                for (int i = 0; i < 2; i++) {
                    int seg = tid + 256 * i;
                    int kr = seg >> 2, o = seg & 3;
                    cp16(slot + kr * KST + o * 16,
                         Kg + (size_t)(t0 + kr) * D_ + d0 + o * 8);
                }
            }
            cp_commit();

            const uint32_t slot = sb + SM_K + (gc & 3) * SLOT_B;
#pragma unroll
            for (int ks = 0; ks < 2; ks++) {
                // A fragments: {a0,a2} at row, {a1,a3} at row+8 (v2 loads).
                const int cb = (c8 * 32 + ks * 16) * 2 + t4 * 8;
                uint32_t a02[2][2], a13[2][2];
#pragma unroll
                for (int mt = 0; mt < 2; mt++) {
                    uint32_t qb = sb + SM_Q +
                        (warpm * 32 + mt * 16 + g) * QST + cb;
                    lds64(a02[mt][0], a02[mt][1], qb);
                    lds64(a13[mt][0], a13[mt][1], qb + 8 * QST);
                }
                uint32_t kb = slot + (warpn * 64 + g) * KST + ks * 32 + t4 * 8;
#pragma unroll
                for (int nb = 0; nb < 8; nb++) {
                    uint32_t b0, b1;
                    lds64(b0, b1, kb + nb * 8 * KST);
                    MMA_BF16(S[0][nb], a02[0][0], a13[0][0], a02[0][1],
                             a13[0][1], b0, b1);
                    MMA_BF16(S[1][nb], a02[1][0], a13[1][0], a02[1][1],
                             a13[1][1], b0, b1);
                }
            }
        }

        // ---- epilogue: p = 2^(s*10*log2e); accumulate l, ax, ay ----
        // c0/c1 at key cols warpn*64 + nb*8 + 2*t4 (+1) ->
        // float4-over-float2 index warpn*32 + nb*4 + t4.
        const float4* __restrict__ C4 = (const float4*)(smem + SM_C);
#pragma unroll
        for (int mt = 0; mt < 2; mt++) {
            const int s0 = mt * 2, s1 = mt * 2 + 1;
#pragma unroll
            for (int nb = 0; nb < 8; nb++) {
                float4 cc = C4[warpn * 32 + nb * 4 + t4];
                float p0 = ex2f(S[mt][nb][0] * SCALE_EX2);
                float p1 = ex2f(S[mt][nb][1] * SCALE_EX2);
                float p2 = ex2f(S[mt][nb][2] * SCALE_EX2);
                float p3 = ex2f(S[mt][nb][3] * SCALE_EX2);
                l[s0] += p0 + p1;
                ax[s0] = fmaf(p0, cc.x, ax[s0]); ay[s0] = fmaf(p0, cc.y, ay[s0]);
                ax[s0] = fmaf(p1, cc.z, ax[s0]); ay[s0] = fmaf(p1, cc.w, ay[s0]);
                l[s1] += p2 + p3;
                ax[s1] = fmaf(p2, cc.x, ax[s1]); ay[s1] = fmaf(p2, cc.y, ay[s1]);
                ax[s1] = fmaf(p3, cc.z, ax[s1]); ay[s1] = fmaf(p3, cc.w, ay[s1]);
            }
        }
    }

    // ---- cross-lane + cross-warpn reduction, then output ----
    float4* __restrict__ red = (float4*)(smem + SM_R);
#pragma unroll
    for (int s = 0; s < 4; s++) {
#pragma unroll
        for (int off = 1; off < 4; off <<= 1) {
            l[s]  += __shfl_xor_sync(0xffffffffu, l[s],  off);
            ax[s] += __shfl_xor_sync(0xffffffffu, ax[s], off);
            ay[s] += __shfl_xor_sync(0xffffffffu, ay[s], off);
        }
        if (t4 == 0) {
            int rowl = warpm * 32 + (s >> 1) * 16 + (s & 1) * 8 + g;
            red[warpn * 128 + rowl] = make_float4(l[s], ax[s], ay[s], 0.f);
        }
    }
    __syncthreads();

    if (tid < 128) {
        float4 r0 = red[tid], r1 = red[128 + tid];
        float lv  = r0.x + r1.x;
        float axv = r0.y + r1.y;
        float ayv = r0.z + r1.z;
        float a = 1.0f / (1.0f + __expf(-alpha_p[0]));
        float inv = 1.0f / lv;
        float wx = axv * inv, wy = ayv * inv;
        float2 c = Cg2[q0 + tid];
        float nx = a * wx + (1.0f - a) * c.x;
        float ny = a * wy + (1.0f - a) * c.y;
        size_t o = ((size_t)b * L_ + q0 + tid) * 2;
        out_new[o + 0]  = nx;
        out_new[o + 1]  = ny;
        out_disp[o + 0] = nx - c.x;
        out_disp[o + 1] = ny - c.y;
    }
}

// ---------------------------------------------------------------------------
// Inputs: latents, current_coords, Wq, Wk, alpha_raw, layer_idx.
// Output: concat(new_coords[B,L,2], displacement[B,L,2]) fp32.
// ---------------------------------------------------------------------------
extern "C" void kernel_launch(void* const* d_in, const int* in_sizes, int n_in,
                              void* d_out, int out_size) {
    const float* latents   = (const float*)d_in[0];
    const float* coords    = (const float*)d_in[1];
    const float* Wq        = (const float*)d_in[2];
    const float* Wk        = (const float*)d_in[3];
    const float* alpha_raw = (const float*)d_in[4];
    float* out = (float*)d_out;

    proj_norm_kernel<<<dim3(BL_ / 32, 2), 128>>>(latents, Wq, Wk);

    cudaFuncSetAttribute(attn_kernel,
                         cudaFuncAttributeMaxDynamicSharedMemorySize, SM_TOT);
    attn_kernel<<<dim3(L_ / 128, B_), 256, SM_TOT>>>(
        coords, alpha_raw, out, out + BL_ * 2);
}

// round 8
// speedup vs baseline: 1.3714x; 1.0622x over previous
#include <cuda_runtime.h>
#include <cuda_bf16.h>
#include <math_constants.h>
#include <cstdint>

#define B_  4
#define L_  4096
#define D_  256
#define BL_ (B_ * L_)
#define NSPLIT 2
#define KEYS_PER_SPLIT (L_ / NSPLIT)        /* 2048 */
#define TILES_PER_SPLIT (KEYS_PER_SPLIT / 128)  /* 16 */
#define CHUNKS_PER_SPLIT (TILES_PER_SPLIT * 8)  /* 128 */

// Scratch (allocation-free device globals), bf16, pair-interleaved d-layout:
// within each 16-d group, pair order [0,4,1,5,2,6,3,7].
__device__ __align__(1024) __nv_bfloat16 g_Q[BL_ * D_];
__device__ __align__(1024) __nv_bfloat16 g_KB[BL_ * D_];
__device__ __align__(1024) float4 g_part[NSPLIT][BL_];   // (l, ax, ay) partials

// ---------------------------------------------------------------------------
// helpers
// ---------------------------------------------------------------------------
__device__ __forceinline__ unsigned long long fma2(unsigned long long a,
                                                   unsigned long long b,
                                                   unsigned long long c) {
    unsigned long long d;
    asm("fma.rn.f32x2 %0, %1, %2, %3;" : "=l"(d) : "l"(a), "l"(b), "l"(c));
    return d;
}

__device__ __forceinline__ uint32_t smem_u32(const void* p) {
    uint32_t a;
    asm("{ .reg .u64 t; cvta.to.shared.u64 t, %1; cvt.u32.u64 %0, t; }"
        : "=r"(a) : "l"(p));
    return a;
}

__device__ __forceinline__ float ex2f(float x) {
    float y;
    asm("ex2.approx.f32 %0, %1;" : "=f"(y) : "f"(x));
    return y;
}

__device__ __forceinline__ void cp16(uint32_t dst, const void* src) {
    asm volatile("cp.async.cg.shared.global [%0], [%1], 16;"
                 :: "r"(dst), "l"(src) : "memory");
}
__device__ __forceinline__ void cp_commit() {
    asm volatile("cp.async.commit_group;" ::: "memory");
}
__device__ __forceinline__ void cp_wait2() {
    asm volatile("cp.async.wait_group 2;" ::: "memory");
}

__device__ __forceinline__ void lds64(uint32_t& v0, uint32_t& v1, uint32_t a) {
    asm volatile("ld.shared.v2.b32 {%0, %1}, [%2];"
                 : "=r"(v0), "=r"(v1) : "r"(a));
}

#define MMA_BF16(d, a0, a1, a2, a3, b0, b1) \
    asm volatile("mma.sync.aligned.m16n8k16.row.col.f32.bf16.bf16.f32 " \
                 "{%0,%1,%2,%3},{%4,%5,%6,%7},{%8,%9},{%0,%1,%2,%3};" \
                 : "+f"((d)[0]), "+f"((d)[1]), "+f"((d)[2]), "+f"((d)[3]) \
                 : "r"(a0), "r"(a1), "r"(a2), "r"(a3), "r"(b0), "r"(b1))

// ---------------------------------------------------------------------------
// Kernel 1: y[r][c] = sum_d X[r][d] * W[c][d], row-L2-normalize, bf16-pack
// with pair-interleaved d-layout. grid.y: 0 -> g_Q, 1 -> g_KB.
// ---------------------------------------------------------------------------
__global__ void __launch_bounds__(128)
proj_norm_kernel(const float* __restrict__ X, const float* __restrict__ Wqp,
                 const float* __restrict__ Wkp) {
    __shared__ __align__(16) float X_s[32][34];
    __shared__ __align__(16) float W_s[256][34];

    const float* __restrict__ W = blockIdx.y ? Wkp : Wqp;

    const int tid = threadIdx.x;
    const int rg  = tid >> 5;
    const int cg  = tid & 31;
    const int row0 = blockIdx.x * 32;

    unsigned long long acc2[8][8];
#pragma unroll
    for (int i = 0; i < 8; i++)
#pragma unroll
        for (int j = 0; j < 8; j++) acc2[i][j] = 0ull;

    for (int d0 = 0; d0 < D_; d0 += 32) {
#pragma unroll
        for (int t = 0; t < 2; t++) {
            int idx = tid + t * 128;
            int r = idx >> 3;
            int d4 = (idx & 7) * 4;
            float4 v = *(const float4*)&X[(row0 + r) * D_ + d0 + d4];
            X_s[r][d4 + 0] = v.x; X_s[r][d4 + 1] = v.y;
            X_s[r][d4 + 2] = v.z; X_s[r][d4 + 3] = v.w;
        }
#pragma unroll
        for (int t = 0; t < 16; t++) {
            int idx = tid + t * 128;
            int c = idx >> 3;
            int d4 = (idx & 7) * 4;
            float4 v = *(const float4*)&W[c * D_ + d0 + d4];
            W_s[c][d4 + 0] = v.x; W_s[c][d4 + 1] = v.y;
            W_s[c][d4 + 2] = v.z; W_s[c][d4 + 3] = v.w;
        }
        __syncthreads();
#pragma unroll 4
        for (int d = 0; d < 32; d += 2) {
            unsigned long long w2[8], x2[8];
#pragma unroll
            for (int cc = 0; cc < 8; cc++)
                w2[cc] = *(const unsigned long long*)&W_s[cc * 32 + cg][d];
#pragma unroll
            for (int ii = 0; ii < 8; ii++)
                x2[ii] = *(const unsigned long long*)&X_s[ii * 4 + rg][d];
#pragma unroll
            for (int ii = 0; ii < 8; ii++)
#pragma unroll
                for (int cc = 0; cc < 8; cc++)
                    acc2[ii][cc] = fma2(x2[ii], w2[cc], acc2[ii][cc]);
        }
        __syncthreads();
    }

    // Stage normalized fp32 into T[d][row] (stride 33 overlay on W_s).
    float* T = &W_s[0][0];

#pragma unroll
    for (int ii = 0; ii < 8; ii++) {
        float dot[8];
        float sq = 0.f;
#pragma unroll
        for (int cc = 0; cc < 8; cc++) {
            unsigned long long v = acc2[ii][cc];
            dot[cc] = __uint_as_float((unsigned)v) +
                      __uint_as_float((unsigned)(v >> 32));
            sq = fmaf(dot[cc], dot[cc], sq);
        }
#pragma unroll
        for (int off = 16; off > 0; off >>= 1)
            sq += __shfl_xor_sync(0xffffffffu, sq, off);
        float scale = 1.0f / fmaxf(sqrtf(sq), 1e-12f);
        int rowl = ii * 4 + rg;
#pragma unroll
        for (int cc = 0; cc < 8; cc++)
            T[(cc * 32 + cg) * 33 + rowl] = dot[cc] * scale;
    }
    __syncthreads();

    // Pack bf16x2 with pair-interleaving.
    __nv_bfloat162* __restrict__ Out =
        (__nv_bfloat162*)(blockIdx.y ? g_KB : g_Q);
#pragma unroll
    for (int it = 0; it < 32; it++) {
        int idx = tid + it * 128;          // 0..4095
        int row = idx >> 7;                // 0..31
        int ps  = idx & 127;               // phys pair-slot in row
        int g16 = ps >> 3, s = ps & 7;
        int j = (s & 1) ? (s >> 1) + 4 : (s >> 1);
        int d = g16 * 16 + 2 * j;
        float lo = T[d * 33 + row];
        float hi = T[(d + 1) * 33 + row];
        Out[(size_t)(row0 + row) * 128 + ps] = __floats2bfloat162_rn(lo, hi);
    }
}

// ---------------------------------------------------------------------------
// Kernel 2: flash attention partials via mma.sync bf16 m16n8k16.
// Grid (32 qtiles, B, 2 key-splits); 2 CTAs co-resident per SM.
// CTA: 128 q x 2048 keys; 256 threads = 8 warps (warpm 0..3, warpn 0..1).
// Warp tile 32(m) x 64(n); K streamed in 32-d x 128-key chunks (ring 4).
// Emits (l, ax, ay) partials; finalize kernel merges the two splits.
// ---------------------------------------------------------------------------
#define QST   528                            /* bytes per Q row (512 + 16) */
#define KST   80                             /* bytes per K row (64 + 16) */
#define SLOT_B (128 * KST)                   /* 10240 */
#define SM_Q   0
#define SM_K   (128 * QST)                   /* 67584 */
#define SM_C   (SM_K + 4 * SLOT_B)           /* 108544 */
#define SM_R   (SM_C + 1024)                 /* 109568 */
#define SM_TOT (SM_R + 4096)                 /* 113664 */

#define SCALE_EX2 14.4269504088896340f       /* 10 * log2(e) */

__global__ void __launch_bounds__(256, 2)
attn_kernel(const float* __restrict__ coords) {
    extern __shared__ __align__(1024) char smem[];
    const uint32_t sb = smem_u32(smem);
    const int tid  = threadIdx.x;
    const int lane = tid & 31;
    const int warp = tid >> 5;
    const int warpm = warp & 3, warpn = warp >> 2;   // 4 x 2 warp grid
    const int g  = lane >> 2, t4 = lane & 3;
    const int b  = blockIdx.y;
    const int q0 = blockIdx.x * 128;
    const int split = blockIdx.z;

    const __nv_bfloat16* __restrict__ Qg = g_Q + (size_t)(b * L_ + q0) * D_;
    const float2* __restrict__ Cg2 = (const float2*)coords + (size_t)b * L_ +
                                     split * KEYS_PER_SPLIT;

    // ---- thread-constant cp.async offsets (32-bit) ----
    // K chunk layout: 4 x 16B per key row; this thread covers 2 rows.
    const int kr0 = tid >> 2,          ko0 = (tid & 3) * 16;        // i = 0
    const int kr1 = (tid + 256) >> 2,  ko1 = ((tid + 256) & 3) * 16;// i = 1
    const uint32_t kdst0 = kr0 * KST + ko0;
    const uint32_t kdst1 = kr1 * KST + ko1;
    // Global element offsets (bf16) within the split's K block.
    const __nv_bfloat16* __restrict__ KgT =
        g_KB + (size_t)(b * L_ + split * KEYS_PER_SPLIT) * D_;
    const int ksrc0 = kr0 * D_ + ko0 / 2;   // 16B = 8 elements
    const int ksrc1 = kr1 * D_ + ko1 / 2;

    // ---- prologue: Q tile + first 3 K chunks via cp.async ----
#pragma unroll
    for (int i = 0; i < 16; i++) {
        int seg = tid + 256 * i;            // 0..4095 (32 x 16B per row)
        int row = seg >> 5, o = seg & 31;
        cp16(sb + SM_Q + row * QST + o * 16, Qg + row * D_ + o * 8);
    }
    cp_commit();
#pragma unroll
    for (int gc = 0; gc < 3; gc++) {
        // chunk gc: tile gc>>3 (=0), d-chunk gc&7
        uint32_t slot = sb + SM_K + (gc & 3) * SLOT_B;
        const __nv_bfloat16* src = KgT + (gc & 7) * 32;
        cp16(slot + kdst0, src + ksrc0);
        cp16(slot + kdst1, src + ksrc1);
        cp_commit();
    }

    float l[4], ax[4], ay[4];
#pragma unroll
    for (int s = 0; s < 4; s++) { l[s] = 0.f; ax[s] = 0.f; ay[s] = 0.f; }

    for (int t = 0; t < TILES_PER_SPLIT; t++) {
        __syncthreads();                    // prev tile epilogue done w/ C_s
        if (tid < 128)
            ((float2*)(smem + SM_C))[tid] = Cg2[t * 128 + tid];

        float S[2][8][4];
#pragma unroll
        for (int mt = 0; mt < 2; mt++)
#pragma unroll
            for (int nb = 0; nb < 8; nb++)
#pragma unroll
                for (int r = 0; r < 4; r++) S[mt][nb][r] = 0.f;

        for (int c8 = 0; c8 < 8; c8++) {
            const int gc = t * 8 + c8;
            cp_wait2();
            __syncthreads();
            // prefetch chunk gc+3 into slot (gc+3)&3 (== (gc-1)&3, now free)
            if (gc + 3 < CHUNKS_PER_SPLIT) {
                int nc = gc + 3;
                uint32_t slot = sb + SM_K + (nc & 3) * SLOT_B;
                const __nv_bfloat16* src =
                    KgT + (nc >> 3) * (128 * D_) + (nc & 7) * 32;
                cp16(slot + kdst0, src + ksrc0);
                cp16(slot + kdst1, src + ksrc1);
            }
            cp_commit();

            const uint32_t slot = sb + SM_K + (gc & 3) * SLOT_B;
#pragma unroll
            for (int ks = 0; ks < 2; ks++) {
                // A fragments: {a0,a2} at row, {a1,a3} at row+8 (v2 loads).
                const int cb = (c8 * 32 + ks * 16) * 2 + t4 * 8;
                uint32_t a02[2][2], a13[2][2];
#pragma unroll
                for (int mt = 0; mt < 2; mt++) {
                    uint32_t qb = sb + SM_Q +
                        (warpm * 32 + mt * 16 + g) * QST + cb;
                    lds64(a02[mt][0], a02[mt][1], qb);
                    lds64(a13[mt][0], a13[mt][1], qb + 8 * QST);
                }
                uint32_t kb = slot + (warpn * 64 + g) * KST + ks * 32 + t4 * 8;
#pragma unroll
                for (int nb = 0; nb < 8; nb++) {
                    uint32_t b0, b1;
                    lds64(b0, b1, kb + nb * 8 * KST);
                    MMA_BF16(S[0][nb], a02[0][0], a13[0][0], a02[0][1],
                             a13[0][1], b0, b1);
                    MMA_BF16(S[1][nb], a02[1][0], a13[1][0], a02[1][1],
                             a13[1][1], b0, b1);
                }
            }
        }

        // ---- epilogue: p = 2^(s*10*log2e); accumulate l, ax, ay ----
        const float4* __restrict__ C4 = (const float4*)(smem + SM_C);
#pragma unroll
        for (int mt = 0; mt < 2; mt++) {
            const int s0 = mt * 2, s1 = mt * 2 + 1;
#pragma unroll
            for (int nb = 0; nb < 8; nb++) {
                float4 cc = C4[warpn * 32 + nb * 4 + t4];
                float p0 = ex2f(S[mt][nb][0] * SCALE_EX2);
                float p1 = ex2f(S[mt][nb][1] * SCALE_EX2);
                float p2 = ex2f(S[mt][nb][2] * SCALE_EX2);
                float p3 = ex2f(S[mt][nb][3] * SCALE_EX2);
                l[s0] += p0 + p1;
                ax[s0] = fmaf(p0, cc.x, ax[s0]); ay[s0] = fmaf(p0, cc.y, ay[s0]);
                ax[s0] = fmaf(p1, cc.z, ax[s0]); ay[s0] = fmaf(p1, cc.w, ay[s0]);
                l[s1] += p2 + p3;
                ax[s1] = fmaf(p2, cc.x, ax[s1]); ay[s1] = fmaf(p2, cc.y, ay[s1]);
                ax[s1] = fmaf(p3, cc.z, ax[s1]); ay[s1] = fmaf(p3, cc.w, ay[s1]);
            }
        }
    }

    // ---- cross-lane + cross-warpn reduction, then write partials ----
    float4* __restrict__ red = (float4*)(smem + SM_R);
#pragma unroll
    for (int s = 0; s < 4; s++) {
#pragma unroll
        for (int off = 1; off < 4; off <<= 1) {
            l[s]  += __shfl_xor_sync(0xffffffffu, l[s],  off);
            ax[s] += __shfl_xor_sync(0xffffffffu, ax[s], off);
            ay[s] += __shfl_xor_sync(0xffffffffu, ay[s], off);
        }
        if (t4 == 0) {
            int rowl = warpm * 32 + (s >> 1) * 16 + (s & 1) * 8 + g;
            red[warpn * 128 + rowl] = make_float4(l[s], ax[s], ay[s], 0.f);
        }
    }
    __syncthreads();

    if (tid < 128) {
        float4 r0 = red[tid], r1 = red[128 + tid];
        g_part[split][b * L_ + q0 + tid] =
            make_float4(r0.x + r1.x, r0.y + r1.y, r0.z + r1.z, 0.f);
    }
}

// ---------------------------------------------------------------------------
// Kernel 3: merge split partials, apply alpha-blend, write outputs.
// ---------------------------------------------------------------------------
__global__ void __launch_bounds__(256)
finalize_kernel(const float* __restrict__ coords,
                const float* __restrict__ alpha_p,
                float* __restrict__ out_new,
                float* __restrict__ out_disp) {
    int i = blockIdx.x * 256 + threadIdx.x;     // 0..BL_-1
    float4 p0 = g_part[0][i];
    float4 p1 = g_part[1][i];
    float lv  = p0.x + p1.x;
    float axv = p0.y + p1.y;
    float ayv = p0.z + p1.z;
    float a = 1.0f / (1.0f + __expf(-alpha_p[0]));
    float inv = 1.0f / lv;
    float wx = axv * inv, wy = ayv * inv;
    float2 c = ((const float2*)coords)[i];
    float nx = a * wx + (1.0f - a) * c.x;
    float ny = a * wy + (1.0f - a) * c.y;
    out_new[2 * i + 0]  = nx;
    out_new[2 * i + 1]  = ny;
    out_disp[2 * i + 0] = nx - c.x;
    out_disp[2 * i + 1] = ny - c.y;
}

// ---------------------------------------------------------------------------
// Inputs: latents, current_coords, Wq, Wk, alpha_raw, layer_idx.
// Output: concat(new_coords[B,L,2], displacement[B,L,2]) fp32.
// ---------------------------------------------------------------------------
extern "C" void kernel_launch(void* const* d_in, const int* in_sizes, int n_in,
                              void* d_out, int out_size) {
    const float* latents   = (const float*)d_in[0];
    const float* coords    = (const float*)d_in[1];
    const float* Wq        = (const float*)d_in[2];
    const float* Wk        = (const float*)d_in[3];
    const float* alpha_raw = (const float*)d_in[4];
    float* out = (float*)d_out;

    proj_norm_kernel<<<dim3(BL_ / 32, 2), 128>>>(latents, Wq, Wk);

    cudaFuncSetAttribute(attn_kernel,
                         cudaFuncAttributeMaxDynamicSharedMemorySize, SM_TOT);
    attn_kernel<<<dim3(L_ / 128, B_, NSPLIT), 256, SM_TOT>>>(coords);

    finalize_kernel<<<BL_ / 256, 256>>>(coords, alpha_raw, out, out + BL_ * 2);
}

// round 9
// speedup vs baseline: 1.9291x; 1.4067x over previous
#include <cuda_runtime.h>
#include <cuda_bf16.h>
#include <math_constants.h>
#include <cstdint>

#define B_  4
#define L_  4096
#define D_  256
#define BL_ (B_ * L_)
#define NSPLIT 2
#define KEYS_PER_SPLIT (L_ / NSPLIT)        /* 2048 */
#define TILES_PER_SPLIT (KEYS_PER_SPLIT / 128)  /* 16 */
#define CHUNKS_PER_SPLIT (TILES_PER_SPLIT * 8)  /* 128 */

// bf16 scratch, pair-interleaved d-layout: within each 16-d group, pair
// order [0,4,1,5,2,6,3,7] (pair j at slot 2j if j<4 else 2(j-4)+1), so
// m16n8k16 fragment words are 8B-contiguous.
__device__ __align__(1024) __nv_bfloat16 g_Q[BL_ * D_];
__device__ __align__(1024) __nv_bfloat16 g_KB[BL_ * D_];
__device__ __align__(1024) __nv_bfloat16 g_Xb[BL_ * D_];
__device__ __align__(1024) __nv_bfloat16 g_Wqb[D_ * D_];
__device__ __align__(1024) __nv_bfloat16 g_Wkb[D_ * D_];
__device__ __align__(1024) float4 g_part[NSPLIT][BL_];   // (l, ax, ay)

// ---------------------------------------------------------------------------
// helpers
// ---------------------------------------------------------------------------
__device__ __forceinline__ uint32_t smem_u32(const void* p) {
    uint32_t a;
    asm("{ .reg .u64 t; cvta.to.shared.u64 t, %1; cvt.u32.u64 %0, t; }"
        : "=r"(a) : "l"(p));
    return a;
}

__device__ __forceinline__ float ex2f(float x) {
    float y;
    asm("ex2.approx.f32 %0, %1;" : "=f"(y) : "f"(x));
    return y;
}

__device__ __forceinline__ void cp16(uint32_t dst, const void* src) {
    asm volatile("cp.async.cg.shared.global [%0], [%1], 16;"
                 :: "r"(dst), "l"(src) : "memory");
}
__device__ __forceinline__ void cp_commit() {
    asm volatile("cp.async.commit_group;" ::: "memory");
}
__device__ __forceinline__ void cp_wait2() {
    asm volatile("cp.async.wait_group 2;" ::: "memory");
}

__device__ __forceinline__ void lds64(uint32_t& v0, uint32_t& v1, uint32_t a) {
    asm volatile("ld.shared.v2.b32 {%0, %1}, [%2];"
                 : "=r"(v0), "=r"(v1) : "r"(a));
}

#define MMA_BF16(d, a0, a1, a2, a3, b0, b1) \
    asm volatile("mma.sync.aligned.m16n8k16.row.col.f32.bf16.bf16.f32 " \
                 "{%0,%1,%2,%3},{%4,%5,%6,%7},{%8,%9},{%0,%1,%2,%3};" \
                 : "+f"((d)[0]), "+f"((d)[1]), "+f"((d)[2]), "+f"((d)[3]) \
                 : "r"(a0), "r"(a1), "r"(a2), "r"(a3), "r"(b0), "r"(b1))

// phys pair-slot for logical pair j within a row (128 pairs)
__device__ __forceinline__ int pslot(int j) {
    int jj = j & 7;
    int s = (jj < 4) ? 2 * jj : 2 * (jj - 4) + 1;
    return (j >> 3) * 8 + s;
}

// ---------------------------------------------------------------------------
// Kernel 0: round latents / Wq / Wk to bf16 in pair-interleaved layout.
// ---------------------------------------------------------------------------
#define XPAIRS (BL_ * 128)
#define WPAIRS (D_ * 128)
#define CVT_TOTAL (XPAIRS + 2 * WPAIRS)

__global__ void __launch_bounds__(256)
convert_kernel(const float* __restrict__ latents,
               const float* __restrict__ Wq, const float* __restrict__ Wk) {
    int idx = blockIdx.x * 256 + threadIdx.x;
    const float* src;
    __nv_bfloat162* dst;
    if (idx < XPAIRS) {
        src = latents; dst = (__nv_bfloat162*)g_Xb;
    } else if (idx < XPAIRS + WPAIRS) {
        idx -= XPAIRS; src = Wq; dst = (__nv_bfloat162*)g_Wqb;
    } else {
        idx -= XPAIRS + WPAIRS; src = Wk; dst = (__nv_bfloat162*)g_Wkb;
    }
    int row = idx >> 7, ps = idx & 127;
    int g16 = ps >> 3, s = ps & 7;
    int j = (s & 1) ? (s >> 1) + 4 : (s >> 1);
    int d = g16 * 16 + 2 * j;
    float lo = __ldg(&src[(size_t)row * D_ + d]);
    float hi = __ldg(&src[(size_t)row * D_ + d + 1]);
    dst[(size_t)row * 128 + ps] = __floats2bfloat162_rn(lo, hi);
}

// ---------------------------------------------------------------------------
// Kernel 1: proj via mma.sync bf16. CTA = 128 rows x 256 cols, K=256.
// grid.y: 0 -> Wq -> g_Q, 1 -> Wk -> g_KB. Row L2-norm fused in epilogue,
// output written bf16x2 pair-interleaved.
// 256 threads = 8 warps (warpm 0..3 x warpn 0..1), warp tile 32m x 128n.
// ---------------------------------------------------------------------------
#define PXST 528                             /* X row bytes (512 + 16) */
#define PWST 80                              /* W row bytes (64 + 16) */
#define P_SLOT (D_ * PWST)                   /* 20480 */
#define P_SMX 0
#define P_SMW (128 * PXST)                   /* 67584 */
#define P_RED (P_SMW + 4 * P_SLOT)           /* 149504 */
#define P_TOT (P_RED + 1024)                 /* 150528 */

__global__ void __launch_bounds__(256, 1)
proj_mma_kernel() {
    extern __shared__ __align__(1024) char smem[];
    const uint32_t sb = smem_u32(smem);
    const int tid  = threadIdx.x;
    const int lane = tid & 31;
    const int warp = tid >> 5;
    const int warpm = warp & 3, warpn = warp >> 2;
    const int g  = lane >> 2, t4 = lane & 3;
    const int row0 = blockIdx.x * 128;

    const __nv_bfloat16* __restrict__ Xg = g_Xb + (size_t)row0 * D_;
    const __nv_bfloat16* __restrict__ Wb = blockIdx.y ? g_Wkb : g_Wqb;

    // W-chunk cp.async thread-constant offsets (4 cp16/thread per chunk).
    const int wn0 = tid >> 2,           wo0 = (tid & 3) * 16;
    const int wn1 = (tid + 256) >> 2,   wo1 = ((tid + 256) & 3) * 16;
    const int wn2 = (tid + 512) >> 2,   wo2 = ((tid + 512) & 3) * 16;
    const int wn3 = (tid + 768) >> 2,   wo3 = ((tid + 768) & 3) * 16;
    const uint32_t wd0 = wn0 * PWST + wo0, wd1 = wn1 * PWST + wo1;
    const uint32_t wd2 = wn2 * PWST + wo2, wd3 = wn3 * PWST + wo3;
    const int ws0 = wn0 * D_ + wo0 / 2, ws1 = wn1 * D_ + wo1 / 2;
    const int ws2 = wn2 * D_ + wo2 / 2, ws3 = wn3 * D_ + wo3 / 2;

    // ---- prologue: X tile (resident) + first 3 W chunks ----
#pragma unroll
    for (int i = 0; i < 16; i++) {
        int seg = tid + 256 * i;            // 0..4095, 32 x 16B per row
        int row = seg >> 5, o = seg & 31;
        cp16(sb + P_SMX + row * PXST + o * 16, Xg + row * D_ + o * 8);
    }
    cp_commit();
#pragma unroll
    for (int gc = 0; gc < 3; gc++) {
        uint32_t slot = sb + P_SMW + (gc & 3) * P_SLOT;
        const __nv_bfloat16* src = Wb + gc * 32;
        cp16(slot + wd0, src + ws0);
        cp16(slot + wd1, src + ws1);
        cp16(slot + wd2, src + ws2);
        cp16(slot + wd3, src + ws3);
        cp_commit();
    }

    float S[2][16][4];
#pragma unroll
    for (int mt = 0; mt < 2; mt++)
#pragma unroll
        for (int nb = 0; nb < 16; nb++)
#pragma unroll
            for (int r = 0; r < 4; r++) S[mt][nb][r] = 0.f;

    for (int gc = 0; gc < 8; gc++) {
        cp_wait2();
        __syncthreads();
        if (gc + 3 < 8) {
            int nc = gc + 3;
            uint32_t slot = sb + P_SMW + (nc & 3) * P_SLOT;
            const __nv_bfloat16* src = Wb + nc * 32;
            cp16(slot + wd0, src + ws0);
            cp16(slot + wd1, src + ws1);
            cp16(slot + wd2, src + ws2);
            cp16(slot + wd3, src + ws3);
        }
        cp_commit();

        const uint32_t slot = sb + P_SMW + (gc & 3) * P_SLOT;
#pragma unroll
        for (int ks = 0; ks < 2; ks++) {
            const int cb = (gc * 32 + ks * 16) * 2 + t4 * 8;
            uint32_t a02[2][2], a13[2][2];
#pragma unroll
            for (int mt = 0; mt < 2; mt++) {
                uint32_t qb = sb + P_SMX + (warpm * 32 + mt * 16 + g) * PXST + cb;
                lds64(a02[mt][0], a02[mt][1], qb);
                lds64(a13[mt][0], a13[mt][1], qb + 8 * PXST);
            }
            uint32_t kb = slot + (warpn * 128 + g) * PWST + ks * 32 + t4 * 8;
#pragma unroll
            for (int nb = 0; nb < 16; nb++) {
                uint32_t b0, b1;
                lds64(b0, b1, kb + nb * 8 * PWST);
                MMA_BF16(S[0][nb], a02[0][0], a13[0][0], a02[0][1], a13[0][1],
                         b0, b1);
                MMA_BF16(S[1][nb], a02[1][0], a13[1][0], a02[1][1], a13[1][1],
                         b0, b1);
            }
        }
    }
    __syncthreads();   // SMEM W/red reuse boundary

    // ---- row sum-of-squares: quad shfl + cross-warpn SMEM exchange ----
    float* __restrict__ red = (float*)(smem + P_RED);
    float ss[2][2];
#pragma unroll
    for (int mt = 0; mt < 2; mt++)
#pragma unroll
        for (int h = 0; h < 2; h++) {
            float v = 0.f;
#pragma unroll
            for (int nb = 0; nb < 16; nb++) {
                v = fmaf(S[mt][nb][2 * h], S[mt][nb][2 * h], v);
                v = fmaf(S[mt][nb][2 * h + 1], S[mt][nb][2 * h + 1], v);
            }
            v += __shfl_xor_sync(0xffffffffu, v, 1);
            v += __shfl_xor_sync(0xffffffffu, v, 2);
            ss[mt][h] = v;
            if (t4 == 0)
                red[warpn * 128 + warpm * 32 + mt * 16 + h * 8 + g] = v;
        }
    __syncthreads();

    // ---- normalize + pack bf16x2 interleaved ----
    __nv_bfloat162* __restrict__ Out =
        (__nv_bfloat162*)(blockIdx.y ? g_KB : g_Q);
#pragma unroll
    for (int mt = 0; mt < 2; mt++)
#pragma unroll
        for (int h = 0; h < 2; h++) {
            int rowl = warpm * 32 + mt * 16 + h * 8 + g;
            float tot = red[rowl] + red[128 + rowl];
            float scale = 1.0f / fmaxf(sqrtf(tot), 1e-12f);
            __nv_bfloat162* orow = Out + (size_t)(row0 + rowl) * 128;
#pragma unroll
            for (int nb = 0; nb < 16; nb++) {
                int j = warpn * 64 + nb * 4 + t4;
                orow[pslot(j)] = __floats2bfloat162_rn(
                    S[mt][nb][2 * h] * scale, S[mt][nb][2 * h + 1] * scale);
            }
        }
}

// ---------------------------------------------------------------------------
// Kernel 2: flash attention partials via mma.sync bf16 m16n8k16.
// Grid (32 qtiles, B, 2 key-splits); 2 CTAs co-resident per SM.
// ---------------------------------------------------------------------------
#define QST   528
#define KST   80
#define SLOT_B (128 * KST)                   /* 10240 */
#define SM_Q   0
#define SM_K   (128 * QST)                   /* 67584 */
#define SM_C   (SM_K + 4 * SLOT_B)           /* 108544 */
#define SM_R   (SM_C + 1024)                 /* 109568 */
#define SM_TOT (SM_R + 4096)                 /* 113664 */

#define SCALE_EX2 14.4269504088896340f       /* 10 * log2(e) */

__global__ void __launch_bounds__(256, 2)
attn_kernel(const float* __restrict__ coords) {
    extern __shared__ __align__(1024) char smem[];
    const uint32_t sb = smem_u32(smem);
    const int tid  = threadIdx.x;
    const int lane = tid & 31;
    const int warp = tid >> 5;
    const int warpm = warp & 3, warpn = warp >> 2;
    const int g  = lane >> 2, t4 = lane & 3;
    const int b  = blockIdx.y;
    const int q0 = blockIdx.x * 128;
    const int split = blockIdx.z;

    const __nv_bfloat16* __restrict__ Qg = g_Q + (size_t)(b * L_ + q0) * D_;
    const float2* __restrict__ Cg2 = (const float2*)coords + (size_t)b * L_ +
                                     split * KEYS_PER_SPLIT;

    const int kr0 = tid >> 2,          ko0 = (tid & 3) * 16;
    const int kr1 = (tid + 256) >> 2,  ko1 = ((tid + 256) & 3) * 16;
    const uint32_t kdst0 = kr0 * KST + ko0;
    const uint32_t kdst1 = kr1 * KST + ko1;
    const __nv_bfloat16* __restrict__ KgT =
        g_KB + (size_t)(b * L_ + split * KEYS_PER_SPLIT) * D_;
    const int ksrc0 = kr0 * D_ + ko0 / 2;
    const int ksrc1 = kr1 * D_ + ko1 / 2;

#pragma unroll
    for (int i = 0; i < 16; i++) {
        int seg = tid + 256 * i;
        int row = seg >> 5, o = seg & 31;
        cp16(sb + SM_Q + row * QST + o * 16, Qg + row * D_ + o * 8);
    }
    cp_commit();
#pragma unroll
    for (int gc = 0; gc < 3; gc++) {
        uint32_t slot = sb + SM_K + (gc & 3) * SLOT_B;
        const __nv_bfloat16* src = KgT + (gc & 7) * 32;
        cp16(slot + kdst0, src + ksrc0);
        cp16(slot + kdst1, src + ksrc1);
        cp_commit();
    }

    float l[4], ax[4], ay[4];
#pragma unroll
    for (int s = 0; s < 4; s++) { l[s] = 0.f; ax[s] = 0.f; ay[s] = 0.f; }

    for (int t = 0; t < TILES_PER_SPLIT; t++) {
        __syncthreads();
        if (tid < 128)
            ((float2*)(smem + SM_C))[tid] = Cg2[t * 128 + tid];

        float S[2][8][4];
#pragma unroll
        for (int mt = 0; mt < 2; mt++)
#pragma unroll
            for (int nb = 0; nb < 8; nb++)
#pragma unroll
                for (int r = 0; r < 4; r++) S[mt][nb][r] = 0.f;

        for (int c8 = 0; c8 < 8; c8++) {
            const int gc = t * 8 + c8;
            cp_wait2();
            __syncthreads();
            if (gc + 3 < CHUNKS_PER_SPLIT) {
                int nc = gc + 3;
                uint32_t slot = sb + SM_K + (nc & 3) * SLOT_B;
                const __nv_bfloat16* src =
                    KgT + (nc >> 3) * (128 * D_) + (nc & 7) * 32;
                cp16(slot + kdst0, src + ksrc0);
                cp16(slot + kdst1, src + ksrc1);
            }
            cp_commit();

            const uint32_t slot = sb + SM_K + (gc & 3) * SLOT_B;
#pragma unroll
            for (int ks = 0; ks < 2; ks++) {
                const int cb = (c8 * 32 + ks * 16) * 2 + t4 * 8;
                uint32_t a02[2][2], a13[2][2];
#pragma unroll
                for (int mt = 0; mt < 2; mt++) {
                    uint32_t qb = sb + SM_Q +
                        (warpm * 32 + mt * 16 + g) * QST + cb;
                    lds64(a02[mt][0], a02[mt][1], qb);
                    lds64(a13[mt][0], a13[mt][1], qb + 8 * QST);
                }
                uint32_t kb = slot + (warpn * 64 + g) * KST + ks * 32 + t4 * 8;
#pragma unroll
                for (int nb = 0; nb < 8; nb++) {
                    uint32_t b0, b1;
                    lds64(b0, b1, kb + nb * 8 * KST);
                    MMA_BF16(S[0][nb], a02[0][0], a13[0][0], a02[0][1],
                             a13[0][1], b0, b1);
                    MMA_BF16(S[1][nb], a02[1][0], a13[1][0], a02[1][1],
                             a13[1][1], b0, b1);
                }
            }
        }

        const float4* __restrict__ C4 = (const float4*)(smem + SM_C);
#pragma unroll
        for (int mt = 0; mt < 2; mt++) {
            const int s0 = mt * 2, s1 = mt * 2 + 1;
#pragma unroll
            for (int nb = 0; nb < 8; nb++) {
                float4 cc = C4[warpn * 32 + nb * 4 + t4];
                float p0 = ex2f(S[mt][nb][0] * SCALE_EX2);
                float p1 = ex2f(S[mt][nb][1] * SCALE_EX2);
                float p2 = ex2f(S[mt][nb][2] * SCALE_EX2);
                float p3 = ex2f(S[mt][nb][3] * SCALE_EX2);
                l[s0] += p0 + p1;
                ax[s0] = fmaf(p0, cc.x, ax[s0]); ay[s0] = fmaf(p0, cc.y, ay[s0]);
                ax[s0] = fmaf(p1, cc.z, ax[s0]); ay[s0] = fmaf(p1, cc.w, ay[s0]);
                l[s1] += p2 + p3;
                ax[s1] = fmaf(p2, cc.x, ax[s1]); ay[s1] = fmaf(p2, cc.y, ay[s1]);
                ax[s1] = fmaf(p3, cc.z, ax[s1]); ay[s1] = fmaf(p3, cc.w, ay[s1]);
            }
        }
    }

    float4* __restrict__ red = (float4*)(smem + SM_R);
#pragma unroll
    for (int s = 0; s < 4; s++) {
#pragma unroll
        for (int off = 1; off < 4; off <<= 1) {
            l[s]  += __shfl_xor_sync(0xffffffffu, l[s],  off);
            ax[s] += __shfl_xor_sync(0xffffffffu, ax[s], off);
            ay[s] += __shfl_xor_sync(0xffffffffu, ay[s], off);
        }
        if (t4 == 0) {
            int rowl = warpm * 32 + (s >> 1) * 16 + (s & 1) * 8 + g;
            red[warpn * 128 + rowl] = make_float4(l[s], ax[s], ay[s], 0.f);
        }
    }
    __syncthreads();

    if (tid < 128) {
        float4 r0 = red[tid], r1 = red[128 + tid];
        g_part[split][b * L_ + q0 + tid] =
            make_float4(r0.x + r1.x, r0.y + r1.y, r0.z + r1.z, 0.f);
    }
}

// ---------------------------------------------------------------------------
// Kernel 3: merge split partials, alpha-blend, write outputs.
// ---------------------------------------------------------------------------
__global__ void __launch_bounds__(256)
finalize_kernel(const float* __restrict__ coords,
                const float* __restrict__ alpha_p,
                float* __restrict__ out_new,
                float* __restrict__ out_disp) {
    int i = blockIdx.x * 256 + threadIdx.x;
    float4 p0 = g_part[0][i];
    float4 p1 = g_part[1][i];
    float lv  = p0.x + p1.x;
    float axv = p0.y + p1.y;
    float ayv = p0.z + p1.z;
    float a = 1.0f / (1.0f + __expf(-alpha_p[0]));
    float inv = 1.0f / lv;
    float wx = axv * inv, wy = ayv * inv;
    float2 c = ((const float2*)coords)[i];
    float nx = a * wx + (1.0f - a) * c.x;
    float ny = a * wy + (1.0f - a) * c.y;
    out_new[2 * i + 0]  = nx;
    out_new[2 * i + 1]  = ny;
    out_disp[2 * i + 0] = nx - c.x;
    out_disp[2 * i + 1] = ny - c.y;
}

// ---------------------------------------------------------------------------
// Inputs: latents, current_coords, Wq, Wk, alpha_raw, layer_idx.
// Output: concat(new_coords[B,L,2], displacement[B,L,2]) fp32.
// ---------------------------------------------------------------------------
extern "C" void kernel_launch(void* const* d_in, const int* in_sizes, int n_in,
                              void* d_out, int out_size) {
    const float* latents   = (const float*)d_in[0];
    const float* coords    = (const float*)d_in[1];
    const float* Wq        = (const float*)d_in[2];
    const float* Wk        = (const float*)d_in[3];
    const float* alpha_raw = (const float*)d_in[4];
    float* out = (float*)d_out;

    convert_kernel<<<CVT_TOTAL / 256, 256>>>(latents, Wq, Wk);

    cudaFuncSetAttribute(proj_mma_kernel,
                         cudaFuncAttributeMaxDynamicSharedMemorySize, P_TOT);
    proj_mma_kernel<<<dim3(BL_ / 128, 2), 256, P_TOT>>>();

    cudaFuncSetAttribute(attn_kernel,
                         cudaFuncAttributeMaxDynamicSharedMemorySize, SM_TOT);
    attn_kernel<<<dim3(L_ / 128, B_, NSPLIT), 256, SM_TOT>>>(coords);

    finalize_kernel<<<BL_ / 256, 256>>>(coords, alpha_raw, out, out + BL_ * 2);
}